// round 14
// baseline (speedup 1.0000x reference)
#include <cuda_runtime.h>
#include <cuda_fp16.h>
#include <cstdint>

// ============================ problem constants ============================
#define N_ROWS 262144
#define CH     256
#define NSEG   16
#define BM     128          // rows per GEMM CTA
#define BN     128          // cols per GEMM CTA
#define SEG_BM 256          // rows per segsum block
#define SEG_RPT 32          // rows per segsum thread (contiguous stripe)
#define BK     64           // k-chunk
#define NCHUNK 4            // 256 / 64
#define BN_EPS 1e-5f

// ============================ smem layout ==================================
#define PA     144                    // bytes per smem row (64 fp16 + 16B pad)
#define A_TILE (BM*PA)                // 18432
#define B_TILE (BN*PA)                // 18432
#define SMEM_TOTAL (2*(A_TILE + B_TILE))   // 73728 -> 2 CTAs/SM

__device__ __forceinline__ int aoff(int buf) { return buf*A_TILE; }
__device__ __forceinline__ int boff(int buf) { return 2*A_TILE + buf*B_TILE; }

// ============================ device scratch ===============================
__device__ float g_sums[NSEG*CH];
__device__ float g_h[NSEG*CH];
__device__ float g_D[NSEG*CH];
__device__ __half g_Wh[CH*CH];             // [n][k] = fp16(W1_top[k][n] * A[n])
__device__ int g_so[NSEG+1];               // {0, o[0..15]}
__device__ __half g_xh[(size_t)N_ROWS*CH]; // fp16 copy of x (produced by pass 1)

// ============================ PTX helpers ==================================
__device__ __forceinline__ uint32_t smem_u32(const void* p) {
    uint32_t a;
    asm("{ .reg .u64 t; cvta.to.shared.u64 t, %1; cvt.u32.u64 %0, t; }"
        : "=r"(a) : "l"(p));
    return a;
}
__device__ __forceinline__ void ldsm4(uint32_t* r, uint32_t addr) {
    asm volatile("ldmatrix.sync.aligned.m8n8.x4.shared.b16 {%0,%1,%2,%3}, [%4];"
                 : "=r"(r[0]), "=r"(r[1]), "=r"(r[2]), "=r"(r[3]) : "r"(addr));
}
__device__ __forceinline__ void mma16816(float* d, const uint32_t* a, uint32_t b0, uint32_t b1) {
    asm volatile("mma.sync.aligned.m16n8k16.row.col.f32.f16.f16.f32 "
                 "{%0,%1,%2,%3},{%4,%5,%6,%7},{%8,%9},{%0,%1,%2,%3};"
                 : "+f"(d[0]), "+f"(d[1]), "+f"(d[2]), "+f"(d[3])
                 : "r"(a[0]), "r"(a[1]), "r"(a[2]), "r"(a[3]), "r"(b0), "r"(b1));
}
__device__ __forceinline__ void cp16(uint32_t dst, const void* src) {
    asm volatile("cp.async.cg.shared.global [%0], [%1], 16;" :: "r"(dst), "l"(src));
}
#define CP_COMMIT() asm volatile("cp.async.commit_group;" ::: "memory")
#define CP_WAIT0()  asm volatile("cp.async.wait_group 0;" ::: "memory")

// ================ kernel 0: zero + offsets + W fp16 prep ===================
__global__ void prep0_kernel(const void* __restrict__ o, const float* __restrict__ W1,
                             const float* __restrict__ gamma, const float* __restrict__ rv) {
    int b = blockIdx.x, c = threadIdx.x;
    if (b < NSEG) {
        g_sums[b*CH + c] = 0.f;
        if (b == 0 && c == 0) {
            const int* oi = (const int*)o;
            bool is64 = (oi[1] == 0);   // int64 LE -> high word of o[0] is 0
            g_so[0] = 0;
            for (int i = 0; i < NSEG; i++)
                g_so[i+1] = is64 ? (int)((const long long*)o)[i] : oi[i];
        }
    } else {
        // W prep: g_Wh[n][k] = fp16(W1_top[k][n]*A[n]); blocks 16..143, 2 rows
        int n2 = b - NSEG;
        #pragma unroll
        for (int sub = 0; sub < 2; ++sub) {
            int n = n2*2 + sub;
            float A = gamma[n] * rsqrtf(rv[n] + BN_EPS);
            g_Wh[n*CH + c] = __float2half_rn(W1[c*CH + n] * A);
        }
    }
}

// ====== kernel 1: segment sums + fp16 conversion (8ch, striped) ===========
__global__ void segsum_kernel(const float* __restrict__ x) {
    __shared__ int so[NSEG+1];
    if (threadIdx.x <= NSEG) so[threadIdx.x] = g_so[threadIdx.x];
    __syncthreads();
    int t = threadIdx.x;
    int c8 = (t & 31) * 8;                       // 8-channel group
    int r0 = blockIdx.x * SEG_BM + (t >> 5) * SEG_RPT;
    int seg = 0;
    while (r0 >= so[seg+1]) seg++;
    float4 a0 = make_float4(0.f,0.f,0.f,0.f), a1 = make_float4(0.f,0.f,0.f,0.f);
    #pragma unroll 8
    for (int j = 0; j < SEG_RPT; j++) {
        int row = r0 + j;
        if (row >= so[seg+1]) {
            atomicAdd(&g_sums[seg*CH + c8 + 0], a0.x);
            atomicAdd(&g_sums[seg*CH + c8 + 1], a0.y);
            atomicAdd(&g_sums[seg*CH + c8 + 2], a0.z);
            atomicAdd(&g_sums[seg*CH + c8 + 3], a0.w);
            atomicAdd(&g_sums[seg*CH + c8 + 4], a1.x);
            atomicAdd(&g_sums[seg*CH + c8 + 5], a1.y);
            atomicAdd(&g_sums[seg*CH + c8 + 6], a1.z);
            atomicAdd(&g_sums[seg*CH + c8 + 7], a1.w);
            a0 = make_float4(0.f,0.f,0.f,0.f); a1 = make_float4(0.f,0.f,0.f,0.f);
            do { seg++; } while (row >= so[seg+1]);
        }
        const float* xp = x + (size_t)row*CH + c8;
        float4 v0 = __ldcs((const float4*)xp);
        float4 v1 = __ldcs((const float4*)(xp + 4));
        __half2 p0 = __float22half2_rn(make_float2(v0.x, v0.y));
        __half2 p1 = __float22half2_rn(make_float2(v0.z, v0.w));
        __half2 p2 = __float22half2_rn(make_float2(v1.x, v1.y));
        __half2 p3 = __float22half2_rn(make_float2(v1.z, v1.w));
        uint4 pk = make_uint4(*(uint32_t*)&p0, *(uint32_t*)&p1,
                              *(uint32_t*)&p2, *(uint32_t*)&p3);
        __stcs((uint4*)(g_xh + (size_t)row*CH + c8), pk);
        a0.x += v0.x; a0.y += v0.y; a0.z += v0.z; a0.w += v0.w;
        a1.x += v1.x; a1.y += v1.y; a1.z += v1.z; a1.w += v1.w;
    }
    atomicAdd(&g_sums[seg*CH + c8 + 0], a0.x);
    atomicAdd(&g_sums[seg*CH + c8 + 1], a0.y);
    atomicAdd(&g_sums[seg*CH + c8 + 2], a0.z);
    atomicAdd(&g_sums[seg*CH + c8 + 3], a0.w);
    atomicAdd(&g_sums[seg*CH + c8 + 4], a1.x);
    atomicAdd(&g_sums[seg*CH + c8 + 5], a1.y);
    atomicAdd(&g_sums[seg*CH + c8 + 6], a1.z);
    atomicAdd(&g_sums[seg*CH + c8 + 7], a1.w);
}

// =========== kernel 2a: h = relu(mean@W2+b2), k-split parallel =============
// grid (NSEG, 8) x 256 threads: block (s, cg) computes h[s, cg*32 .. +32)
__global__ void h_kernel(const float* __restrict__ W2, const float* __restrict__ b2) {
    __shared__ float red[256];
    int s = blockIdx.x, cg = blockIdx.y;
    int t = threadIdx.x;
    int c = cg*32 + (t & 31);      // output channel
    int kg = t >> 5;               // k group (8 groups of 32)
    float inv = 1.f / (float)(g_so[s+1] - g_so[s]);
    float acc = 0.f;
    #pragma unroll 8
    for (int kk = 0; kk < 32; kk++) {
        int k = kg*32 + kk;
        acc = fmaf(g_sums[s*CH + k] * inv, W2[k*CH + c], acc);
    }
    red[t] = acc;
    __syncthreads();
    if (t < 64) { red[t] = (red[t] + red[t+64]) + (red[t+128] + red[t+192]); }
    __syncthreads();
    if (t < 32) {
        float v = red[t] + red[t+32] + b2[c];
        g_h[s*CH + c] = fmaxf(v, 0.f);
    }
}

// =========== kernel 2b: D = BN-affine(h@W1_bot + b1), k-split ==============
__global__ void d_kernel(const float* __restrict__ W1, const float* __restrict__ b1,
                         const float* __restrict__ gamma, const float* __restrict__ beta,
                         const float* __restrict__ rm, const float* __restrict__ rv) {
    __shared__ float red[256];
    int s = blockIdx.x, cg = blockIdx.y;
    int t = threadIdx.x;
    int c = cg*32 + (t & 31);
    int kg = t >> 5;
    float acc = 0.f;
    #pragma unroll 8
    for (int kk = 0; kk < 32; kk++) {
        int k = kg*32 + kk;
        acc = fmaf(g_h[s*CH + k], W1[(CH + k)*CH + c], acc);
    }
    red[t] = acc;
    __syncthreads();
    if (t < 64) { red[t] = (red[t] + red[t+64]) + (red[t+128] + red[t+192]); }
    __syncthreads();
    if (t < 32) {
        float v = red[t] + red[t+32] + b1[c];
        float A = gamma[c] * rsqrtf(rv[c] + BN_EPS);
        g_D[s*CH + c] = v * A + (beta[c] - rm[c] * A);
    }
}

// ============================ GEMM pieces ==================================
__device__ __forceinline__ void issue_AB(uint32_t sb, size_t row0, int nbase,
                                         int kc, int buf, int tid) {
    #pragma unroll
    for (int i = 0; i < 4; ++i) {          // A: 1024 x 16B
        int idx = tid + i*256;
        int r = idx >> 3, q = idx & 7;
        cp16(sb + aoff(buf) + r*PA + q*16, g_xh + (row0 + (size_t)r)*CH + kc*BK + q*8);
    }
    #pragma unroll
    for (int i = 0; i < 4; ++i) {          // B: 1024 x 16B
        int idx = tid + i*256;
        int n = idx >> 3, q = idx & 7;
        cp16(sb + boff(buf) + n*PA + q*16, g_Wh + (size_t)(nbase + n)*CH + kc*BK + q*8);
    }
    CP_COMMIT();
}

// ============================ kernel 3: mma.sync GEMM + epilogue ===========
// grid (CH/BN, N_ROWS/BM): the two N-halves of a row tile are adjacent bids
// -> co-resident -> second A-tile read hits L2.
__global__ __launch_bounds__(256, 2)
void gemm_kernel(float* __restrict__ out) {
    extern __shared__ char smem[];
    __shared__ int sso[NSEG+1];
    uint32_t sb = smem_u32(smem);
    int tid = threadIdx.x, lane = tid & 31, wid = tid >> 5;
    int wm = wid & 3;          // warp row block: 32 rows (4 blocks)
    int wn = wid >> 2;         // warp col block: 64 cols (2 blocks)
    size_t row0 = (size_t)blockIdx.y * BM;
    int nbase = blockIdx.x * BN;

    if (tid <= NSEG) sso[tid] = g_so[tid];

    float acc[2][8][4];
    #pragma unroll
    for (int mt = 0; mt < 2; mt++)
        #pragma unroll
        for (int nt = 0; nt < 8; nt++)
            #pragma unroll
            for (int i = 0; i < 4; i++) acc[mt][nt][i] = 0.f;

    // ---- prologue: chunk 0 into buf 0 (R6 schedule) ----
    issue_AB(sb, row0, nbase, 0, 0, tid);
    CP_WAIT0();
    __syncthreads();

    // ---- main loop: issue(next) -> compute(cur) -> wait -> sync ----
    for (int kc = 0; kc < NCHUNK; ++kc) {
        int cur = kc & 1, nxt = cur ^ 1;
        if (kc < NCHUNK-1) issue_AB(sb, row0, nbase, kc+1, nxt, tid);

        uint32_t arow = sb + aoff(cur) + (wm*32 + (lane & 15))*PA + ((lane >> 4) << 3)*2;
        uint32_t brow = sb + boff(cur) + (wn*64 + (lane & 7) + ((lane >> 4) << 3))*PA
                              + (((lane >> 3) & 1) * 8)*2;
        #pragma unroll
        for (int ks = 0; ks < 4; ++ks) {
            uint32_t a0[4], a1[4];
            ldsm4(a0, arow + ks*32);
            ldsm4(a1, arow + ks*32 + 16*PA);
            #pragma unroll
            for (int ntp = 0; ntp < 4; ++ntp) {
                uint32_t b[4];
                ldsm4(b, brow + ntp*16*PA + ks*32);
                mma16816(acc[0][ntp*2+0], a0, b[0], b[1]);
                mma16816(acc[0][ntp*2+1], a0, b[2], b[3]);
                mma16816(acc[1][ntp*2+0], a1, b[0], b[1]);
                mma16816(acc[1][ntp*2+1], a1, b[2], b[3]);
            }
        }
        CP_WAIT0();
        __syncthreads();
    }

    // ---- epilogue: + D[seg], ReLU, streaming store ----
    int r = lane >> 2, c2 = (lane & 3) * 2;
    #pragma unroll
    for (int mt = 0; mt < 2; mt++) {
        #pragma unroll
        for (int half = 0; half < 2; half++) {
            int m = wm*32 + mt*16 + half*8 + r;
            size_t grow = row0 + (size_t)m;
            int seg = 0;
            while ((int)grow >= sso[seg+1]) seg++;
            const float* Drow = g_D + seg*CH;
            float* orow = out + grow*CH;
            #pragma unroll
            for (int nt = 0; nt < 8; nt++) {
                int col = nbase + wn*64 + nt*8 + c2;
                float v0 = acc[mt][nt][half*2+0] + Drow[col];
                float v1 = acc[mt][nt][half*2+1] + Drow[col+1];
                __stcs((float2*)(orow + col), make_float2(fmaxf(v0, 0.f), fmaxf(v1, 0.f)));
            }
        }
    }
}

// ============================ launch ======================================
extern "C" void kernel_launch(void* const* d_in, const int* in_sizes, int n_in,
                              void* d_out, int out_size) {
    const float* x     = (const float*)d_in[0];
    const void*  o     = d_in[1];
    const float* W2    = (const float*)d_in[2];
    const float* b2    = (const float*)d_in[3];
    const float* W1    = (const float*)d_in[4];
    const float* b1    = (const float*)d_in[5];
    const float* gamma = (const float*)d_in[6];
    const float* beta  = (const float*)d_in[7];
    const float* rm    = (const float*)d_in[8];
    const float* rv    = (const float*)d_in[9];
    float* out = (float*)d_out;

    cudaFuncSetAttribute(gemm_kernel, cudaFuncAttributeMaxDynamicSharedMemorySize, SMEM_TOTAL);

    prep0_kernel<<<NSEG + CH/2, CH>>>(o, W1, gamma, rv);
    segsum_kernel<<<N_ROWS/SEG_BM, 256>>>(x);
    h_kernel<<<dim3(NSEG, 8), 256>>>(W2, b2);
    d_kernel<<<dim3(NSEG, 8), 256>>>(W1, b1, gamma, beta, rm, rv);
    gemm_kernel<<<dim3(CH/BN, N_ROWS/BM), 256, SMEM_TOTAL>>>(out);
}

// round 15
// speedup vs baseline: 1.2406x; 1.2406x over previous
#include <cuda_runtime.h>
#include <cuda_fp16.h>
#include <cstdint>

// ============================ problem constants ============================
#define N_ROWS 262144
#define CH     256
#define NSEG   16
#define BM     128          // rows per GEMM CTA
#define BN     128          // cols per GEMM CTA
#define SEG_BM 256          // rows per segsum block
#define SEG_RPT 64          // rows per segsum thread (contiguous stripe)
#define BK     64           // k-chunk
#define NCHUNK 4            // 256 / 64
#define BN_EPS 1e-5f

// ============================ smem layout ==================================
#define PA     144                    // bytes per smem row (64 fp16 + 16B pad)
#define A_TILE (BM*PA)                // 18432
#define B_TILE (BN*PA)                // 18432
#define SMEM_TOTAL (2*(A_TILE + B_TILE))   // 73728 -> 2 CTAs/SM

__device__ __forceinline__ int aoff(int buf) { return buf*A_TILE; }
__device__ __forceinline__ int boff(int buf) { return 2*A_TILE + buf*B_TILE; }

// ============================ device scratch ===============================
__device__ float g_sums[NSEG*CH];
__device__ float g_D[NSEG*CH];
__device__ __half g_Wh[CH*CH];             // [n][k] = fp16(W1_top[k][n] * A[n])
__device__ int g_so[NSEG+1];               // {0, o[0..15]}
__device__ __half g_xh[(size_t)N_ROWS*CH]; // fp16 copy of x (produced by pass 1)

// ============================ PTX helpers ==================================
__device__ __forceinline__ uint32_t smem_u32(const void* p) {
    uint32_t a;
    asm("{ .reg .u64 t; cvta.to.shared.u64 t, %1; cvt.u32.u64 %0, t; }"
        : "=r"(a) : "l"(p));
    return a;
}
__device__ __forceinline__ void ldsm4(uint32_t* r, uint32_t addr) {
    asm volatile("ldmatrix.sync.aligned.m8n8.x4.shared.b16 {%0,%1,%2,%3}, [%4];"
                 : "=r"(r[0]), "=r"(r[1]), "=r"(r[2]), "=r"(r[3]) : "r"(addr));
}
__device__ __forceinline__ void mma16816(float* d, const uint32_t* a, uint32_t b0, uint32_t b1) {
    asm volatile("mma.sync.aligned.m16n8k16.row.col.f32.f16.f16.f32 "
                 "{%0,%1,%2,%3},{%4,%5,%6,%7},{%8,%9},{%0,%1,%2,%3};"
                 : "+f"(d[0]), "+f"(d[1]), "+f"(d[2]), "+f"(d[3])
                 : "r"(a[0]), "r"(a[1]), "r"(a[2]), "r"(a[3]), "r"(b0), "r"(b1));
}
__device__ __forceinline__ void cp16(uint32_t dst, const void* src) {
    asm volatile("cp.async.cg.shared.global [%0], [%1], 16;" :: "r"(dst), "l"(src));
}
#define CP_COMMIT() asm volatile("cp.async.commit_group;" ::: "memory")
#define CP_WAIT0()  asm volatile("cp.async.wait_group 0;" ::: "memory")

// ============================ kernel 0: zero + decode offsets ==============
__global__ void prep0_kernel(const void* __restrict__ o) {
    int t = blockIdx.x * blockDim.x + threadIdx.x;
    if (t < NSEG*CH) g_sums[t] = 0.f;
    if (t == 0) {
        const int* oi = (const int*)o;
        bool is64 = (oi[1] == 0);   // int64 LE -> high word of o[0] is 0
        g_so[0] = 0;
        for (int i = 0; i < NSEG; i++)
            g_so[i+1] = is64 ? (int)((const long long*)o)[i] : oi[i];
    }
}

// ====== kernel 1: segment sums + fp16 conversion (float4, striped) =========
__global__ void segsum_kernel(const float* __restrict__ x) {
    __shared__ int so[NSEG+1];
    if (threadIdx.x <= NSEG) so[threadIdx.x] = g_so[threadIdx.x];
    __syncthreads();
    int t = threadIdx.x;
    int c4 = (t & 63) * 4;                       // channel group (float4)
    int r0 = blockIdx.x * SEG_BM + (t >> 6) * SEG_RPT;
    int seg = 0;
    while (r0 >= so[seg+1]) seg++;
    float4 acc = make_float4(0.f, 0.f, 0.f, 0.f);
    #pragma unroll 8
    for (int j = 0; j < SEG_RPT; j++) {
        int row = r0 + j;
        if (row >= so[seg+1]) {
            atomicAdd(&g_sums[seg*CH + c4 + 0], acc.x);
            atomicAdd(&g_sums[seg*CH + c4 + 1], acc.y);
            atomicAdd(&g_sums[seg*CH + c4 + 2], acc.z);
            atomicAdd(&g_sums[seg*CH + c4 + 3], acc.w);
            acc = make_float4(0.f, 0.f, 0.f, 0.f);
            do { seg++; } while (row >= so[seg+1]);
        }
        float4 v = __ldcs((const float4*)(x + (size_t)row*CH + c4));
        __half2 p0 = __float22half2_rn(make_float2(v.x, v.y));
        __half2 p1 = __float22half2_rn(make_float2(v.z, v.w));
        __stcs((uint2*)(g_xh + (size_t)row*CH + c4),
               make_uint2(*(uint32_t*)&p0, *(uint32_t*)&p1));
        acc.x += v.x; acc.y += v.y; acc.z += v.z; acc.w += v.w;
    }
    atomicAdd(&g_sums[seg*CH + c4 + 0], acc.x);
    atomicAdd(&g_sums[seg*CH + c4 + 1], acc.y);
    atomicAdd(&g_sums[seg*CH + c4 + 2], acc.z);
    atomicAdd(&g_sums[seg*CH + c4 + 3], acc.w);
}

// ================= kernel 2: fused h -> D  +  W fp16 prep ==================
__global__ void fused_prep_kernel(const float* __restrict__ W2, const float* __restrict__ b2,
                                  const float* __restrict__ W1, const float* __restrict__ b1,
                                  const float* __restrict__ gamma, const float* __restrict__ beta,
                                  const float* __restrict__ rm, const float* __restrict__ rv) {
    int b = blockIdx.x, c = threadIdx.x;
    if (b < NSEG) {
        __shared__ float m[CH], hs[CH];
        int s = b;
        float cnt = (float)(g_so[s+1] - g_so[s]);
        m[c] = g_sums[s*CH + c] / cnt;
        __syncthreads();
        float acc = b2[c];
        #pragma unroll 16
        for (int k = 0; k < CH; k++) acc = fmaf(m[k], W2[k*CH + c], acc);
        hs[c] = fmaxf(acc, 0.f);
        __syncthreads();
        float acc2 = b1[c];
        #pragma unroll 16
        for (int k = 0; k < CH; k++) acc2 = fmaf(hs[k], W1[(CH + k)*CH + c], acc2);
        float A = gamma[c] * rsqrtf(rv[c] + BN_EPS);
        g_D[s*CH + c] = acc2 * A + (beta[c] - rm[c] * A);
    } else {
        int n2 = b - NSEG;
        #pragma unroll
        for (int sub = 0; sub < 2; ++sub) {
            int n = n2*2 + sub;
            float A = gamma[n] * rsqrtf(rv[n] + BN_EPS);
            g_Wh[n*CH + c] = __float2half_rn(W1[c*CH + n] * A);
        }
    }
}

// ============================ GEMM pieces ==================================
// cp.async A (128 rows) + B (128 rows) fp16 tiles of chunk kc into buffer buf.
__device__ __forceinline__ void issue_AB(uint32_t sb, size_t row0, int nbase,
                                         int kc, int buf, int tid) {
    #pragma unroll
    for (int i = 0; i < 4; ++i) {          // A: 1024 x 16B
        int idx = tid + i*256;
        int r = idx >> 3, q = idx & 7;
        cp16(sb + aoff(buf) + r*PA + q*16, g_xh + (row0 + (size_t)r)*CH + kc*BK + q*8);
    }
    #pragma unroll
    for (int i = 0; i < 4; ++i) {          // B: 1024 x 16B
        int idx = tid + i*256;
        int n = idx >> 3, q = idx & 7;
        cp16(sb + boff(buf) + n*PA + q*16, g_Wh + (size_t)(nbase + n)*CH + kc*BK + q*8);
    }
    CP_COMMIT();
}

// ============================ kernel 3: mma.sync GEMM + epilogue ===========
// Exact R6 schedule (best measured: 157.4us): depth-1, 2 buffers,
// issue(next) -> compute(cur) -> wait0 -> sync. Grid (rows, N-halves).
__global__ __launch_bounds__(256, 2)
void gemm_kernel(float* __restrict__ out) {
    extern __shared__ char smem[];
    __shared__ int sso[NSEG+1];
    uint32_t sb = smem_u32(smem);
    int tid = threadIdx.x, lane = tid & 31, wid = tid >> 5;
    int wm = wid & 3;          // warp row block: 32 rows (4 blocks)
    int wn = wid >> 2;         // warp col block: 64 cols (2 blocks)
    size_t row0 = (size_t)blockIdx.x * BM;
    int nbase = blockIdx.y * BN;

    if (tid <= NSEG) sso[tid] = g_so[tid];

    float acc[2][8][4];
    #pragma unroll
    for (int mt = 0; mt < 2; mt++)
        #pragma unroll
        for (int nt = 0; nt < 8; nt++)
            #pragma unroll
            for (int i = 0; i < 4; i++) acc[mt][nt][i] = 0.f;

    // ---- prologue: chunk 0 into buf 0 ----
    issue_AB(sb, row0, nbase, 0, 0, tid);
    CP_WAIT0();
    __syncthreads();

    // ---- main loop over K chunks ----
    for (int kc = 0; kc < NCHUNK; ++kc) {
        int cur = kc & 1, nxt = cur ^ 1;
        if (kc < NCHUNK-1) issue_AB(sb, row0, nbase, kc+1, nxt, tid);

        uint32_t arow = sb + aoff(cur) + (wm*32 + (lane & 15))*PA + ((lane >> 4) << 3)*2;
        uint32_t brow = sb + boff(cur) + (wn*64 + (lane & 7) + ((lane >> 4) << 3))*PA
                              + (((lane >> 3) & 1) * 8)*2;
        #pragma unroll
        for (int ks = 0; ks < 4; ++ks) {
            uint32_t a0[4], a1[4];
            ldsm4(a0, arow + ks*32);
            ldsm4(a1, arow + ks*32 + 16*PA);
            #pragma unroll
            for (int ntp = 0; ntp < 4; ++ntp) {
                uint32_t b[4];
                ldsm4(b, brow + ntp*16*PA + ks*32);
                mma16816(acc[0][ntp*2+0], a0, b[0], b[1]);
                mma16816(acc[0][ntp*2+1], a0, b[2], b[3]);
                mma16816(acc[1][ntp*2+0], a1, b[0], b[1]);
                mma16816(acc[1][ntp*2+1], a1, b[2], b[3]);
            }
        }
        CP_WAIT0();
        __syncthreads();
    }

    // ---- epilogue: + D[seg], ReLU, streaming store ----
    int r = lane >> 2, c2 = (lane & 3) * 2;
    #pragma unroll
    for (int mt = 0; mt < 2; mt++) {
        #pragma unroll
        for (int half = 0; half < 2; half++) {
            int m = wm*32 + mt*16 + half*8 + r;
            size_t grow = row0 + (size_t)m;
            int seg = 0;
            while ((int)grow >= sso[seg+1]) seg++;
            const float* Drow = g_D + seg*CH;
            float* orow = out + grow*CH;
            #pragma unroll
            for (int nt = 0; nt < 8; nt++) {
                int col = nbase + wn*64 + nt*8 + c2;
                float v0 = acc[mt][nt][half*2+0] + Drow[col];
                float v1 = acc[mt][nt][half*2+1] + Drow[col+1];
                __stcs((float2*)(orow + col), make_float2(fmaxf(v0, 0.f), fmaxf(v1, 0.f)));
            }
        }
    }
}

// ============================ launch ======================================
extern "C" void kernel_launch(void* const* d_in, const int* in_sizes, int n_in,
                              void* d_out, int out_size) {
    const float* x     = (const float*)d_in[0];
    const void*  o     = d_in[1];
    const float* W2    = (const float*)d_in[2];
    const float* b2    = (const float*)d_in[3];
    const float* W1    = (const float*)d_in[4];
    const float* b1    = (const float*)d_in[5];
    const float* gamma = (const float*)d_in[6];
    const float* beta  = (const float*)d_in[7];
    const float* rm    = (const float*)d_in[8];
    const float* rv    = (const float*)d_in[9];
    float* out = (float*)d_out;

    cudaFuncSetAttribute(gemm_kernel, cudaFuncAttributeMaxDynamicSharedMemorySize, SMEM_TOTAL);

    prep0_kernel<<<16, 256>>>(o);
    segsum_kernel<<<N_ROWS/SEG_BM, 256>>>(x);
    fused_prep_kernel<<<NSEG + CH/2, CH>>>(W2, b2, W1, b1, gamma, beta, rm, rv);
    gemm_kernel<<<dim3(N_ROWS/BM, CH/BN), 256, SMEM_TOTAL>>>(out);
}

// round 16
// speedup vs baseline: 1.2647x; 1.0194x over previous
#include <cuda_runtime.h>
#include <cuda_fp16.h>
#include <cstdint>

// ============================ problem constants ============================
#define N_ROWS 262144
#define CH     256
#define NSEG   16
#define BM     128          // rows per GEMM CTA
#define BN     128          // cols per GEMM CTA
#define SEG_BM 256          // rows per segsum block
#define SEG_RPT 64          // rows per segsum thread (contiguous stripe)
#define BK     64           // k-chunk
#define NCHUNK 4            // 256 / 64
#define BN_EPS 1e-5f

// ============================ smem layout ==================================
#define PA     144                    // bytes per smem row (64 fp16 + 16B pad)
#define A_TILE (BM*PA)                // 18432
#define B_TILE (BN*PA)                // 18432
#define SMEM_TOTAL (2*(A_TILE + B_TILE))   // 73728 -> 2 CTAs/SM

__device__ __forceinline__ int aoff(int buf) { return buf*A_TILE; }
__device__ __forceinline__ int boff(int buf) { return 2*A_TILE + buf*B_TILE; }

// ============================ device scratch ===============================
__device__ float g_sums[NSEG*CH];
__device__ float g_D[NSEG*CH];
__device__ __half g_Wh[CH*CH];             // [n][k] = fp16(W1_top[k][n] * A[n])
__device__ int g_so[NSEG+1];               // {0, o[0..15]}
__device__ __half g_xh[(size_t)N_ROWS*CH]; // fp16 copy of x (produced by pass 1)

// ============================ PTX helpers ==================================
__device__ __forceinline__ uint32_t smem_u32(const void* p) {
    uint32_t a;
    asm("{ .reg .u64 t; cvta.to.shared.u64 t, %1; cvt.u32.u64 %0, t; }"
        : "=r"(a) : "l"(p));
    return a;
}
__device__ __forceinline__ void ldsm4(uint32_t* r, uint32_t addr) {
    asm volatile("ldmatrix.sync.aligned.m8n8.x4.shared.b16 {%0,%1,%2,%3}, [%4];"
                 : "=r"(r[0]), "=r"(r[1]), "=r"(r[2]), "=r"(r[3]) : "r"(addr));
}
__device__ __forceinline__ void mma16816(float* d, const uint32_t* a, uint32_t b0, uint32_t b1) {
    asm volatile("mma.sync.aligned.m16n8k16.row.col.f32.f16.f16.f32 "
                 "{%0,%1,%2,%3},{%4,%5,%6,%7},{%8,%9},{%0,%1,%2,%3};"
                 : "+f"(d[0]), "+f"(d[1]), "+f"(d[2]), "+f"(d[3])
                 : "r"(a[0]), "r"(a[1]), "r"(a[2]), "r"(a[3]), "r"(b0), "r"(b1));
}
__device__ __forceinline__ void cp16(uint32_t dst, const void* src) {
    asm volatile("cp.async.cg.shared.global [%0], [%1], 16;" :: "r"(dst), "l"(src));
}
#define CP_COMMIT() asm volatile("cp.async.commit_group;" ::: "memory")
#define CP_WAIT0()  asm volatile("cp.async.wait_group 0;" ::: "memory")

// ============================ kernel 0: zero + decode offsets ==============
__global__ void prep0_kernel(const void* __restrict__ o) {
    int t = blockIdx.x * blockDim.x + threadIdx.x;
    if (t < NSEG*CH) g_sums[t] = 0.f;
    if (t == 0) {
        const int* oi = (const int*)o;
        bool is64 = (oi[1] == 0);   // int64 LE -> high word of o[0] is 0
        g_so[0] = 0;
        for (int i = 0; i < NSEG; i++)
            g_so[i+1] = is64 ? (int)((const long long*)o)[i] : oi[i];
    }
}

// ====== kernel 1: segment sums + fp16 conversion (float4, striped) =========
__global__ void segsum_kernel(const float* __restrict__ x) {
    __shared__ int so[NSEG+1];
    if (threadIdx.x <= NSEG) so[threadIdx.x] = g_so[threadIdx.x];
    __syncthreads();
    int t = threadIdx.x;
    int c4 = (t & 63) * 4;                       // channel group (float4)
    int r0 = blockIdx.x * SEG_BM + (t >> 6) * SEG_RPT;
    int seg = 0;
    while (r0 >= so[seg+1]) seg++;
    float4 acc = make_float4(0.f, 0.f, 0.f, 0.f);
    #pragma unroll 8
    for (int j = 0; j < SEG_RPT; j++) {
        int row = r0 + j;
        if (row >= so[seg+1]) {
            atomicAdd(&g_sums[seg*CH + c4 + 0], acc.x);
            atomicAdd(&g_sums[seg*CH + c4 + 1], acc.y);
            atomicAdd(&g_sums[seg*CH + c4 + 2], acc.z);
            atomicAdd(&g_sums[seg*CH + c4 + 3], acc.w);
            acc = make_float4(0.f, 0.f, 0.f, 0.f);
            do { seg++; } while (row >= so[seg+1]);
        }
        float4 v = __ldcs((const float4*)(x + (size_t)row*CH + c4));
        __half2 p0 = __float22half2_rn(make_float2(v.x, v.y));
        __half2 p1 = __float22half2_rn(make_float2(v.z, v.w));
        __stcs((uint2*)(g_xh + (size_t)row*CH + c4),
               make_uint2(*(uint32_t*)&p0, *(uint32_t*)&p1));
        acc.x += v.x; acc.y += v.y; acc.z += v.z; acc.w += v.w;
    }
    atomicAdd(&g_sums[seg*CH + c4 + 0], acc.x);
    atomicAdd(&g_sums[seg*CH + c4 + 1], acc.y);
    atomicAdd(&g_sums[seg*CH + c4 + 2], acc.z);
    atomicAdd(&g_sums[seg*CH + c4 + 3], acc.w);
}

// ================= kernel 2: fused h -> D  +  W fp16 prep ==================
__global__ void fused_prep_kernel(const float* __restrict__ W2, const float* __restrict__ b2,
                                  const float* __restrict__ W1, const float* __restrict__ b1,
                                  const float* __restrict__ gamma, const float* __restrict__ beta,
                                  const float* __restrict__ rm, const float* __restrict__ rv) {
    int b = blockIdx.x, c = threadIdx.x;
    if (b < NSEG) {
        __shared__ float m[CH], hs[CH];
        int s = b;
        float cnt = (float)(g_so[s+1] - g_so[s]);
        m[c] = g_sums[s*CH + c] / cnt;
        __syncthreads();
        float acc = b2[c];
        #pragma unroll 16
        for (int k = 0; k < CH; k++) acc = fmaf(m[k], W2[k*CH + c], acc);
        hs[c] = fmaxf(acc, 0.f);
        __syncthreads();
        float acc2 = b1[c];
        #pragma unroll 16
        for (int k = 0; k < CH; k++) acc2 = fmaf(hs[k], W1[(CH + k)*CH + c], acc2);
        float A = gamma[c] * rsqrtf(rv[c] + BN_EPS);
        g_D[s*CH + c] = acc2 * A + (beta[c] - rm[c] * A);
    } else {
        int n2 = b - NSEG;
        #pragma unroll
        for (int sub = 0; sub < 2; ++sub) {
            int n = n2*2 + sub;
            float A = gamma[n] * rsqrtf(rv[n] + BN_EPS);
            g_Wh[n*CH + c] = __float2half_rn(W1[c*CH + n] * A);
        }
    }
}

// ============================ GEMM pieces ==================================
// cp.async A (128 rows) + B (128 rows) fp16 tiles of chunk kc into buffer buf.
__device__ __forceinline__ void issue_AB(uint32_t sb, size_t row0, int nbase,
                                         int kc, int buf, int tid) {
    #pragma unroll
    for (int i = 0; i < 4; ++i) {          // A: 1024 x 16B
        int idx = tid + i*256;
        int r = idx >> 3, q = idx & 7;
        cp16(sb + aoff(buf) + r*PA + q*16, g_xh + (row0 + (size_t)r)*CH + kc*BK + q*8);
    }
    #pragma unroll
    for (int i = 0; i < 4; ++i) {          // B: 1024 x 16B
        int idx = tid + i*256;
        int n = idx >> 3, q = idx & 7;
        cp16(sb + boff(buf) + n*PA + q*16, g_Wh + (size_t)(nbase + n)*CH + kc*BK + q*8);
    }
    CP_COMMIT();
}

// ============================ kernel 3: mma.sync GEMM + epilogue ===========
// R6 schedule (best measured). 1D grid, bid-swizzled: the two N-halves of a
// row tile are ADJACENT bids -> co-resident -> second A-tile read hits L2.
__global__ __launch_bounds__(256, 2)
void gemm_kernel(float* __restrict__ out) {
    extern __shared__ char smem[];
    __shared__ int sso[NSEG+1];
    uint32_t sb = smem_u32(smem);
    int tid = threadIdx.x, lane = tid & 31, wid = tid >> 5;
    int wm = wid & 3;          // warp row block: 32 rows (4 blocks)
    int wn = wid >> 2;         // warp col block: 64 cols (2 blocks)
    int bx = blockIdx.x;
    size_t row0 = (size_t)(bx >> 1) * BM;
    int nbase = (bx & 1) * BN;

    if (tid <= NSEG) sso[tid] = g_so[tid];

    float acc[2][8][4];
    #pragma unroll
    for (int mt = 0; mt < 2; mt++)
        #pragma unroll
        for (int nt = 0; nt < 8; nt++)
            #pragma unroll
            for (int i = 0; i < 4; i++) acc[mt][nt][i] = 0.f;

    // ---- prologue: chunk 0 into buf 0 ----
    issue_AB(sb, row0, nbase, 0, 0, tid);
    CP_WAIT0();
    __syncthreads();

    // ---- main loop over K chunks ----
    for (int kc = 0; kc < NCHUNK; ++kc) {
        int cur = kc & 1, nxt = cur ^ 1;
        if (kc < NCHUNK-1) issue_AB(sb, row0, nbase, kc+1, nxt, tid);

        uint32_t arow = sb + aoff(cur) + (wm*32 + (lane & 15))*PA + ((lane >> 4) << 3)*2;
        uint32_t brow = sb + boff(cur) + (wn*64 + (lane & 7) + ((lane >> 4) << 3))*PA
                              + (((lane >> 3) & 1) * 8)*2;
        #pragma unroll
        for (int ks = 0; ks < 4; ++ks) {
            uint32_t a0[4], a1[4];
            ldsm4(a0, arow + ks*32);
            ldsm4(a1, arow + ks*32 + 16*PA);
            #pragma unroll
            for (int ntp = 0; ntp < 4; ++ntp) {
                uint32_t b[4];
                ldsm4(b, brow + ntp*16*PA + ks*32);
                mma16816(acc[0][ntp*2+0], a0, b[0], b[1]);
                mma16816(acc[0][ntp*2+1], a0, b[2], b[3]);
                mma16816(acc[1][ntp*2+0], a1, b[0], b[1]);
                mma16816(acc[1][ntp*2+1], a1, b[2], b[3]);
            }
        }
        CP_WAIT0();
        __syncthreads();
    }

    // ---- epilogue: + D[seg], ReLU, streaming store ----
    int r = lane >> 2, c2 = (lane & 3) * 2;
    #pragma unroll
    for (int mt = 0; mt < 2; mt++) {
        #pragma unroll
        for (int half = 0; half < 2; half++) {
            int m = wm*32 + mt*16 + half*8 + r;
            size_t grow = row0 + (size_t)m;
            int seg = 0;
            while ((int)grow >= sso[seg+1]) seg++;
            const float* Drow = g_D + seg*CH;
            float* orow = out + grow*CH;
            #pragma unroll
            for (int nt = 0; nt < 8; nt++) {
                int col = nbase + wn*64 + nt*8 + c2;
                float v0 = acc[mt][nt][half*2+0] + Drow[col];
                float v1 = acc[mt][nt][half*2+1] + Drow[col+1];
                __stcs((float2*)(orow + col), make_float2(fmaxf(v0, 0.f), fmaxf(v1, 0.f)));
            }
        }
    }
}

// ============================ launch ======================================
extern "C" void kernel_launch(void* const* d_in, const int* in_sizes, int n_in,
                              void* d_out, int out_size) {
    const float* x     = (const float*)d_in[0];
    const void*  o     = d_in[1];
    const float* W2    = (const float*)d_in[2];
    const float* b2    = (const float*)d_in[3];
    const float* W1    = (const float*)d_in[4];
    const float* b1    = (const float*)d_in[5];
    const float* gamma = (const float*)d_in[6];
    const float* beta  = (const float*)d_in[7];
    const float* rm    = (const float*)d_in[8];
    const float* rv    = (const float*)d_in[9];
    float* out = (float*)d_out;

    cudaFuncSetAttribute(gemm_kernel, cudaFuncAttributeMaxDynamicSharedMemorySize, SMEM_TOTAL);

    prep0_kernel<<<16, 256>>>(o);
    segsum_kernel<<<N_ROWS/SEG_BM, 256>>>(x);
    fused_prep_kernel<<<NSEG + CH/2, CH>>>(W2, b2, W1, b1, gamma, beta, rm, rv);
    gemm_kernel<<<(N_ROWS/BM) * (CH/BN), 256, SMEM_TOTAL>>>(out);
}